// round 6
// baseline (speedup 1.0000x reference)
#include <cuda_runtime.h>
#include <stdint.h>

// ============================================================================
// HeteroscedasticSoftmax: out = mean_{s<100} softmax(logits + eps_s * exp(log_std))
// eps_s reproduces jax.random.normal(split(key(1),100)[s], [8,19,256,256])
// bit-exactly (partitionable threefry2x32; 32-bit draw = x0_out ^ x1_out;
// XLA/Giles erfinv).
//
// R6: alu pipe was saturated (busy 2.39ms = Threefry SHF+LOP3 floor) while fma
// idled at 1.39ms. Convert 6/20 rotations per draw to IMAD pairs
// (lo = x*2^r; rot = IMAD.HI(x, 2^r, lo), disjoint-bit add == or) with opaque
// register multipliers so ptxas can't strength-reduce. Both pipes ~2.05ms.
// ============================================================================

#define NSAMP 100
#define NCH   19
#define NB    8
#define HW    65536            // 256*256

// Opaque constants — loaded from memory so ptxas cannot const-fold IMADs into
// IADD3/SHF (pipe placement is the whole point).
__device__ uint32_t d_one = 1u;
__device__ uint32_t d_c26 = 1u << 26;
__device__ uint32_t d_c16 = 1u << 16;
__device__ uint32_t d_c6  = 1u << 6;

__device__ __forceinline__ uint32_t imad1(uint32_t a, uint32_t one, uint32_t b) {
  uint32_t r;
  asm("mad.lo.u32 %0, %1, %2, %3;" : "=r"(r) : "r"(a), "r"(one), "r"(b));
  return r;
}
__device__ __forceinline__ uint32_t imad_lo(uint32_t a, uint32_t c) {
  uint32_t r;
  asm("mul.lo.u32 %0, %1, %2;" : "=r"(r) : "r"(a), "r"(c));
  return r;
}
__device__ __forceinline__ uint32_t imad_hi(uint32_t a, uint32_t c, uint32_t b) {
  uint32_t r;
  asm("mad.hi.u32 %0, %1, %2, %3;" : "=r"(r) : "r"(a), "r"(c), "r"(b));
  return r;
}

// (bits >> 9) + 0x3F800000 on the fma pipe (IMAD.HI); equals OR (disjoint bits).
__device__ __forceinline__ uint32_t mantissa_to_one_two(uint32_t bits) {
  uint32_t r;
  asm("mad.hi.u32 %0, %1, %2, %3;" : "=r"(r)
      : "r"(bits), "n"(1u << 23), "n"(0x3F800000u));
  return r;
}

__device__ __forceinline__ float ex2_approx(float x) {
  float r; asm("ex2.approx.f32 %0, %1;" : "=f"(r) : "f"(x)); return r;
}
__device__ __forceinline__ float lg2_approx(float x) {
  float r; asm("lg2.approx.f32 %0, %1;" : "=f"(r) : "f"(x)); return r;
}

// Threefry2x32 (20 rounds), adds on fma pipe; rotations r=26/16/first-6 done
// as IMAD pairs (fma pipe), rest as SHF (alu pipe). Caller pre-injects
// (x0 = k0, x1 = ctr + k1). Returns x0^x1 (jax partitionable 32-bit draw).
__device__ __forceinline__ uint32_t threefry2x32_x(
    uint32_t x0, uint32_t x1,
    uint32_t j1a, uint32_t j1b, uint32_t j2a, uint32_t j2b,
    uint32_t j3a, uint32_t j3b, uint32_t j4a, uint32_t j4b,
    uint32_t j5a, uint32_t j5b,
    uint32_t one, uint32_t c26, uint32_t c16, uint32_t c6) {
#define TF_ROUND_S(r) { x0 = imad1(x0, one, x1); x1 = __funnelshift_l(x1, x1, (r)); x1 ^= x0; }
#define TF_ROUND_M(c) { x0 = imad1(x0, one, x1); uint32_t lo_ = imad_lo(x1, (c)); x1 = imad_hi(x1, (c), lo_); x1 ^= x0; }
#define TF_INJ(a, b) { x0 = imad1(x0, one, (a)); x1 = imad1(x1, one, (b)); }
  TF_ROUND_S(13) TF_ROUND_S(15) TF_ROUND_M(c26) TF_ROUND_M(c6)
  TF_INJ(j1a, j1b)
  TF_ROUND_S(17) TF_ROUND_S(29) TF_ROUND_M(c16) TF_ROUND_S(24)
  TF_INJ(j2a, j2b)
  TF_ROUND_S(13) TF_ROUND_S(15) TF_ROUND_M(c26) TF_ROUND_S(6)
  TF_INJ(j3a, j3b)
  TF_ROUND_S(17) TF_ROUND_S(29) TF_ROUND_M(c16) TF_ROUND_S(24)
  TF_INJ(j4a, j4b)
  TF_ROUND_S(13) TF_ROUND_S(15) TF_ROUND_M(c26) TF_ROUND_S(6)
  TF_INJ(j5a, j5b)
#undef TF_ROUND_S
#undef TF_ROUND_M
#undef TF_INJ
  return x0 ^ x1;
}

// Plain version (key derivation only; once per block).
__device__ __forceinline__ uint2 threefry2x32(uint32_t k0, uint32_t k1,
                                              uint32_t x0, uint32_t x1) {
  uint32_t k2 = k0 ^ k1 ^ 0x1BD11BDAu;
  x0 += k0; x1 += k1;
#define TF_ROUND(r) { x0 += x1; x1 = __funnelshift_l(x1, x1, (r)); x1 ^= x0; }
  TF_ROUND(13) TF_ROUND(15) TF_ROUND(26) TF_ROUND(6)
  x0 += k1; x1 += k2 + 1u;
  TF_ROUND(17) TF_ROUND(29) TF_ROUND(16) TF_ROUND(24)
  x0 += k2; x1 += k0 + 2u;
  TF_ROUND(13) TF_ROUND(15) TF_ROUND(26) TF_ROUND(6)
  x0 += k0; x1 += k1 + 3u;
  TF_ROUND(17) TF_ROUND(29) TF_ROUND(16) TF_ROUND(24)
  x0 += k1; x1 += k2 + 4u;
  TF_ROUND(13) TF_ROUND(15) TF_ROUND(26) TF_ROUND(6)
  x0 += k2; x1 += k0 + 5u;
#undef TF_ROUND
  return make_uint2(x0, x1);
}

#define JAX_LO (-0.99999994f)          // nextafter(-1, 0) in fp32
#define NEG_LN2 (-0.69314718f)
// w = -ln2*lg2(y); branch "w < 5"  <=>  lg2(y) > 5/-ln2
#define LG2_BRANCH (-7.21347520f)

// XLA ErfInv32 (Giles) WITHOUT the final sqrt2 (folded into sd prescale).
__device__ __forceinline__ float erfinv_raw(float x) {
  float y = fmaf(-x, x, 1.0f);          // 1 - x^2
  float wl = lg2_approx(y);             // lg2(y); w = -ln2 * wl
  float p;
  if (wl > LG2_BRANCH) {                // common path (w < 5), ~99.66%
    float w = fmaf(wl, NEG_LN2, -2.5f); // w - 2.5 fused
    p = 2.81022636e-08f;
    p = fmaf(p, w, 3.43273939e-07f);
    p = fmaf(p, w, -3.5233877e-06f);
    p = fmaf(p, w, -4.39150654e-06f);
    p = fmaf(p, w, 0.00021858087f);
    p = fmaf(p, w, -0.00125372503f);
    p = fmaf(p, w, -0.00417768164f);
    p = fmaf(p, w, 0.246640727f);
    p = fmaf(p, w, 1.50140941f);
  } else {
    float w = sqrtf(wl * NEG_LN2) - 3.0f;
    p = -0.000200214257f;
    p = fmaf(p, w, 0.000100950558f);
    p = fmaf(p, w, 0.00134934322f);
    p = fmaf(p, w, -0.00367342844f);
    p = fmaf(p, w, 0.00573950773f);
    p = fmaf(p, w, -0.0076224613f);
    p = fmaf(p, w, 0.00943887047f);
    p = fmaf(p, w, 1.00167406f);
    p = fmaf(p, w, 2.83297682f);
  }
  return p * x;
}

__device__ __forceinline__ float bits_to_eps_raw(uint32_t bits) {
  float g = __uint_as_float(mantissa_to_one_two(bits));  // [1, 2)
  float f = g - 1.0f;                                    // exact
  float u = fmaf(f, 2.0f, JAX_LO);   // == XLA mul+add; clamp is a proven no-op
  return erfinv_raw(u);              // sqrt2 folded into sd prescale
}

#define LOG2E 1.44269504f
#define SQRT2_LOG2E 2.04009342f       // sqrt(2) * log2(e)

__global__ __launch_bounds__(128, 8)
void hs_main_kernel(const float* __restrict__ in, float* __restrict__ out) {
  __shared__ uint2 sk[NSAMP];
  __shared__ float2 lgsd[NCH][128];   // (.x = logits*log2e, .y = std*sqrt2*log2e)
  int t = threadIdx.x;
  // Derive the 100 sample keys from jax.random.key(1) = (0, 1) in-block.
  if (t < NSAMP) sk[t] = threefry2x32(0u, 1u, 0u, (uint32_t)t);

  const uint32_t one = d_one;
  const uint32_t c26 = d_c26, c16 = d_c16, c6 = d_c6;

  unsigned T = blockIdx.x * 128u + (unsigned)t;   // 0 .. 524287
  unsigned b = T >> 16;
  unsigned hw = T & 0xFFFFu;

  const float* pin = in + (size_t)b * (2 * NCH) * HW + hw;
#pragma unroll
  for (int c = 0; c < NCH; c++) {
    float l = pin[(size_t)c * HW];
    float s = __expf(pin[(size_t)(NCH + c) * HW]);
    lgsd[c][t] = make_float2(l * LOG2E, s * SQRT2_LOG2E);
  }
  __syncthreads();

  float acc[NCH];
#pragma unroll
  for (int c = 0; c < NCH; c++) acc[c] = 0.0f;

  const uint32_t ctrBase = b * (NCH * HW) + hw;   // flat idx of (b, 0, hw)

#pragma unroll 1
  for (int s = 0; s < NSAMP; s++) {
    const uint2 k = sk[s];
    const uint32_t k0 = k.x, k1 = k.y;
    const uint32_t k2 = k0 ^ k1 ^ 0x1BD11BDAu;
    const uint32_t j1b = k2 + 1u, j2b = k0 + 2u, j3b = k1 + 3u,
                   j4b = k2 + 4u, j5b = k0 + 5u;
    const uint32_t x1base = ctrBase + k1;   // counter lo + initial k1 inject
    float z[NCH];
#pragma unroll
    for (int c = 0; c < NCH; c++) {
      // counter = (0, ctrBase + c*HW); x0 init = 0 + k0.
      uint32_t x1 = imad1(x1base, one, (uint32_t)c << 16);
      uint32_t bits = threefry2x32_x(k0, x1,
                                     k1, j1b, k2, j2b, k0, j3b,
                                     k1, j4b, k2, j5b,
                                     one, c26, c16, c6);
      float er = bits_to_eps_raw(bits);
      float2 ls = lgsd[c][t];
      z[c] = fmaf(er, ls.y, ls.x);       // log2-domain logits+eps*std
    }
    // softmax over channels in log2 domain (max needed: |z| can reach ~600)
    float m = z[0];
#pragma unroll
    for (int c = 1; c < NCH; c++) m = fmaxf(m, z[c]);
    float sum = 0.0f;
#pragma unroll
    for (int c = 0; c < NCH; c++) {
      float e = ex2_approx(z[c] - m);
      z[c] = e;
      sum += e;
    }
    float inv = __fdividef(0.01f, sum);  // 1/NSAMP folded in
#pragma unroll
    for (int c = 0; c < NCH; c++) acc[c] = fmaf(z[c], inv, acc[c]);
  }

  float* pout = out + (size_t)b * NCH * HW + hw;
#pragma unroll
  for (int c = 0; c < NCH; c++) pout[(size_t)c * HW] = acc[c];
}

extern "C" void kernel_launch(void* const* d_in, const int* in_sizes, int n_in,
                              void* d_out, int out_size) {
  (void)in_sizes; (void)n_in; (void)out_size;
  const float* in = (const float*)d_in[0];
  float* out = (float*)d_out;

  // 8 batches * 65536 spatial = 524288 threads, one per (b, h, w)
  hs_main_kernel<<<4096, 128>>>(in, out);
}

// round 7
// speedup vs baseline: 1.1321x; 1.1321x over previous
#include <cuda_runtime.h>
#include <stdint.h>

// ============================================================================
// HeteroscedasticSoftmax: out = mean_{s<100} softmax(logits + eps_s * exp(log_std))
// eps_s reproduces jax.random.normal(split(key(1),100)[s], [8,19,256,256])
// bit-exactly (partitionable threefry2x32; draw = x0^x1; XLA/Giles erfinv).
//
// R7: R6's rotate-IMAD reverted (latency regression). New: channel-split —
// each pixel handled by a THREAD PAIR (10/9 channels) to halve z/acc register
// state -> 12 blocks/SM occupancy. Softmax max/sum joined via shfl_xor(1).
// Dummy channel row 19 = (-INF, 0) makes the odd thread's 10th slot a no-op.
// ============================================================================

#define NSAMP 100
#define NCH   19
#define NB    8
#define HW    65536            // 256*256

// Opaque 1 — keeps integer adds as IMAD (fma pipe) instead of IADD3 (alu).
__device__ uint32_t d_one = 1u;

__device__ __forceinline__ uint32_t imad1(uint32_t a, uint32_t one, uint32_t b) {
  uint32_t r;
  asm("mad.lo.u32 %0, %1, %2, %3;" : "=r"(r) : "r"(a), "r"(one), "r"(b));
  return r;
}

// (bits >> 9) + 0x3F800000 on the fma pipe (IMAD.HI); equals OR (disjoint bits).
__device__ __forceinline__ uint32_t mantissa_to_one_two(uint32_t bits) {
  uint32_t r;
  asm("mad.hi.u32 %0, %1, %2, %3;" : "=r"(r)
      : "r"(bits), "n"(1u << 23), "n"(0x3F800000u));
  return r;
}

__device__ __forceinline__ float ex2_approx(float x) {
  float r; asm("ex2.approx.f32 %0, %1;" : "=f"(r) : "f"(x)); return r;
}
__device__ __forceinline__ float lg2_approx(float x) {
  float r; asm("lg2.approx.f32 %0, %1;" : "=f"(r) : "f"(x)); return r;
}

// Threefry2x32 (20 rounds), adds on fma pipe (IMAD), rotations on SHF.
// Caller pre-injects (x0 = k0, x1 = ctr + k1). Returns x0^x1.
__device__ __forceinline__ uint32_t threefry2x32_x(
    uint32_t x0, uint32_t x1,
    uint32_t j1a, uint32_t j1b, uint32_t j2a, uint32_t j2b,
    uint32_t j3a, uint32_t j3b, uint32_t j4a, uint32_t j4b,
    uint32_t j5a, uint32_t j5b, uint32_t one) {
#define TF_ROUND(r) { x0 = imad1(x0, one, x1); x1 = __funnelshift_l(x1, x1, (r)); x1 ^= x0; }
#define TF_INJ(a, b) { x0 = imad1(x0, one, (a)); x1 = imad1(x1, one, (b)); }
  TF_ROUND(13) TF_ROUND(15) TF_ROUND(26) TF_ROUND(6)
  TF_INJ(j1a, j1b)
  TF_ROUND(17) TF_ROUND(29) TF_ROUND(16) TF_ROUND(24)
  TF_INJ(j2a, j2b)
  TF_ROUND(13) TF_ROUND(15) TF_ROUND(26) TF_ROUND(6)
  TF_INJ(j3a, j3b)
  TF_ROUND(17) TF_ROUND(29) TF_ROUND(16) TF_ROUND(24)
  TF_INJ(j4a, j4b)
  TF_ROUND(13) TF_ROUND(15) TF_ROUND(26) TF_ROUND(6)
  TF_INJ(j5a, j5b)
#undef TF_ROUND
#undef TF_INJ
  return x0 ^ x1;
}

// Plain version (key derivation only; once per block).
__device__ __forceinline__ uint2 threefry2x32(uint32_t k0, uint32_t k1,
                                              uint32_t x0, uint32_t x1) {
  uint32_t k2 = k0 ^ k1 ^ 0x1BD11BDAu;
  x0 += k0; x1 += k1;
#define TF_ROUND(r) { x0 += x1; x1 = __funnelshift_l(x1, x1, (r)); x1 ^= x0; }
  TF_ROUND(13) TF_ROUND(15) TF_ROUND(26) TF_ROUND(6)
  x0 += k1; x1 += k2 + 1u;
  TF_ROUND(17) TF_ROUND(29) TF_ROUND(16) TF_ROUND(24)
  x0 += k2; x1 += k0 + 2u;
  TF_ROUND(13) TF_ROUND(15) TF_ROUND(26) TF_ROUND(6)
  x0 += k0; x1 += k1 + 3u;
  TF_ROUND(17) TF_ROUND(29) TF_ROUND(16) TF_ROUND(24)
  x0 += k1; x1 += k2 + 4u;
  TF_ROUND(13) TF_ROUND(15) TF_ROUND(26) TF_ROUND(6)
  x0 += k2; x1 += k0 + 5u;
#undef TF_ROUND
  return make_uint2(x0, x1);
}

#define JAX_LO (-0.99999994f)          // nextafter(-1, 0) in fp32
#define NEG_LN2 (-0.69314718f)
// w = -ln2*lg2(y); branch "w < 5"  <=>  lg2(y) > 5/-ln2
#define LG2_BRANCH (-7.21347520f)

// XLA ErfInv32 (Giles) WITHOUT the final sqrt2 (folded into sd prescale).
__device__ __forceinline__ float erfinv_raw(float x) {
  float y = fmaf(-x, x, 1.0f);          // 1 - x^2
  float wl = lg2_approx(y);             // lg2(y); w = -ln2 * wl
  float p;
  if (wl > LG2_BRANCH) {                // common path (w < 5), ~99.66%
    float w = fmaf(wl, NEG_LN2, -2.5f); // w - 2.5 fused
    p = 2.81022636e-08f;
    p = fmaf(p, w, 3.43273939e-07f);
    p = fmaf(p, w, -3.5233877e-06f);
    p = fmaf(p, w, -4.39150654e-06f);
    p = fmaf(p, w, 0.00021858087f);
    p = fmaf(p, w, -0.00125372503f);
    p = fmaf(p, w, -0.00417768164f);
    p = fmaf(p, w, 0.246640727f);
    p = fmaf(p, w, 1.50140941f);
  } else {
    float w = sqrtf(wl * NEG_LN2) - 3.0f;
    p = -0.000200214257f;
    p = fmaf(p, w, 0.000100950558f);
    p = fmaf(p, w, 0.00134934322f);
    p = fmaf(p, w, -0.00367342844f);
    p = fmaf(p, w, 0.00573950773f);
    p = fmaf(p, w, -0.0076224613f);
    p = fmaf(p, w, 0.00943887047f);
    p = fmaf(p, w, 1.00167406f);
    p = fmaf(p, w, 2.83297682f);
  }
  return p * x;
}

__device__ __forceinline__ float bits_to_eps_raw(uint32_t bits) {
  float g = __uint_as_float(mantissa_to_one_two(bits));  // [1, 2)
  float f = g - 1.0f;                                    // exact
  float u = fmaf(f, 2.0f, JAX_LO);   // == XLA mul+add; clamp is a proven no-op
  return erfinv_raw(u);              // sqrt2 folded into sd prescale
}

#define LOG2E 1.44269504f
#define SQRT2_LOG2E 2.04009342f       // sqrt(2) * log2(e)
#define NCH_T 10                       // channels per thread (pair: 10 + 9+dummy)

__global__ __launch_bounds__(128, 12)
void hs_main_kernel(const float* __restrict__ in, float* __restrict__ out) {
  __shared__ uint2 sk[NSAMP];
  __shared__ float2 lgsd[NCH + 1][64];  // row NCH = dummy (-INF, 0)
  int t = threadIdx.x;
  // Derive the 100 sample keys from jax.random.key(1) = (0, 1) in-block.
  if (t < NSAMP) sk[t] = threefry2x32(0u, 1u, 0u, (uint32_t)t);

  const uint32_t one = d_one;

  const int slot = t >> 1;          // pixel slot within block (0..63)
  const int h   = t & 1;            // half: 0 -> channels 0..9, 1 -> 10..18
  const int h10 = h * NCH_T;

  unsigned P = blockIdx.x * 64u + (unsigned)slot;   // pixel 0 .. 524287
  unsigned b = P >> 16;
  unsigned hw = P & 0xFFFFu;

  const float* pin = in + (size_t)b * (2 * NCH) * HW + hw;
#pragma unroll
  for (int i = 0; i < NCH_T; i++) {
    int c = h10 + i;
    if (c < NCH) {
      float l = pin[(size_t)c * HW];
      float s = __expf(pin[(size_t)(NCH + c) * HW]);
      lgsd[c][slot] = make_float2(l * LOG2E, s * SQRT2_LOG2E);
    } else {
      // dummy channel: z = fmaf(er, 0, -INF) = -INF -> exp contribution 0
      lgsd[NCH][slot] = make_float2(__int_as_float(0xFF800000), 0.0f);
    }
  }
  __syncthreads();

  float acc[NCH_T];
#pragma unroll
  for (int i = 0; i < NCH_T; i++) acc[i] = 0.0f;

  const uint32_t ctrBase = b * (NCH * HW) + hw;   // flat idx of (b, 0, hw)

#pragma unroll 1
  for (int s = 0; s < NSAMP; s++) {
    const uint2 k = sk[s];
    const uint32_t k0 = k.x, k1 = k.y;
    const uint32_t k2 = k0 ^ k1 ^ 0x1BD11BDAu;
    const uint32_t j1b = k2 + 1u, j2b = k0 + 2u, j3b = k1 + 3u,
                   j4b = k2 + 4u, j5b = k0 + 5u;
    const uint32_t x1base = ctrBase + k1;   // counter lo + initial k1 inject
    float z[NCH_T];
#pragma unroll
    for (int i = 0; i < NCH_T; i++) {
      uint32_t c = (uint32_t)(h10 + i);
      // counter = (0, ctrBase + c*HW); x0 init = 0 + k0.
      uint32_t x1 = imad1(x1base, one, c << 16);
      uint32_t bits = threefry2x32_x(k0, x1,
                                     k1, j1b, k2, j2b, k0, j3b,
                                     k1, j4b, k2, j5b, one);
      float er = bits_to_eps_raw(bits);
      float2 ls = lgsd[c][slot];
      z[i] = fmaf(er, ls.y, ls.x);       // log2-domain logits+eps*std
    }
    // softmax over all 19 channels: local reduce + pair-lane shfl join
    float m = z[0];
#pragma unroll
    for (int i = 1; i < NCH_T; i++) m = fmaxf(m, z[i]);
    m = fmaxf(m, __shfl_xor_sync(0xFFFFFFFFu, m, 1));
    float sum = 0.0f;
#pragma unroll
    for (int i = 0; i < NCH_T; i++) {
      float e = ex2_approx(z[i] - m);
      z[i] = e;
      sum += e;
    }
    sum += __shfl_xor_sync(0xFFFFFFFFu, sum, 1);
    float inv = __fdividef(0.01f, sum);  // 1/NSAMP folded in
#pragma unroll
    for (int i = 0; i < NCH_T; i++) acc[i] = fmaf(z[i], inv, acc[i]);
  }

  float* pout = out + (size_t)b * NCH * HW + hw;
#pragma unroll
  for (int i = 0; i < NCH_T; i++) {
    int c = h10 + i;
    if (c < NCH) pout[(size_t)c * HW] = acc[i];
  }
}

extern "C" void kernel_launch(void* const* d_in, const int* in_sizes, int n_in,
                              void* d_out, int out_size) {
  (void)in_sizes; (void)n_in; (void)out_size;
  const float* in = (const float*)d_in[0];
  float* out = (float*)d_out;

  // 524288 pixels, 2 threads per pixel, 64 pixels per 128-thread block
  hs_main_kernel<<<8192, 128>>>(in, out);
}

// round 8
// speedup vs baseline: 1.1640x; 1.0282x over previous
#include <cuda_runtime.h>
#include <stdint.h>

// ============================================================================
// HeteroscedasticSoftmax: out = mean_{s<100} softmax(logits + eps_s * exp(log_std))
// eps_s reproduces jax.random.normal(split(key(1),100)[s], [8,19,256,256])
// bit-exactly (partitionable threefry2x32; draw = x0^x1; XLA/Giles erfinv).
//
// R8: base = R5 (best, 3644us: 19 ch/thread, smem lg/sd, log2-domain softmax).
// + tree (depth-5) max & sum reductions instead of 18-deep serial chains
//   (removes ~140 low-ILP cycles per sample per thread).
// + launch_bounds(128, 9): R5 measured 55 regs, 9-block cap needs <=56.
// ============================================================================

#define NSAMP 100
#define NCH   19
#define NB    8
#define HW    65536            // 256*256

// Opaque 1 — keeps integer adds as IMAD (fma pipe) instead of IADD3 (alu).
__device__ uint32_t d_one = 1u;

__device__ __forceinline__ uint32_t imad1(uint32_t a, uint32_t one, uint32_t b) {
  uint32_t r;
  asm("mad.lo.u32 %0, %1, %2, %3;" : "=r"(r) : "r"(a), "r"(one), "r"(b));
  return r;
}

// (bits >> 9) + 0x3F800000 on the fma pipe (IMAD.HI); equals OR (disjoint bits).
__device__ __forceinline__ uint32_t mantissa_to_one_two(uint32_t bits) {
  uint32_t r;
  asm("mad.hi.u32 %0, %1, %2, %3;" : "=r"(r)
      : "r"(bits), "n"(1u << 23), "n"(0x3F800000u));
  return r;
}

__device__ __forceinline__ float ex2_approx(float x) {
  float r; asm("ex2.approx.f32 %0, %1;" : "=f"(r) : "f"(x)); return r;
}
__device__ __forceinline__ float lg2_approx(float x) {
  float r; asm("lg2.approx.f32 %0, %1;" : "=f"(r) : "f"(x)); return r;
}

// Threefry2x32 (20 rounds), adds on fma pipe (IMAD), rotations on SHF.
// Caller pre-injects (x0 = k0, x1 = ctr + k1). Returns x0^x1.
__device__ __forceinline__ uint32_t threefry2x32_x(
    uint32_t x0, uint32_t x1,
    uint32_t j1a, uint32_t j1b, uint32_t j2a, uint32_t j2b,
    uint32_t j3a, uint32_t j3b, uint32_t j4a, uint32_t j4b,
    uint32_t j5a, uint32_t j5b, uint32_t one) {
#define TF_ROUND(r) { x0 = imad1(x0, one, x1); x1 = __funnelshift_l(x1, x1, (r)); x1 ^= x0; }
#define TF_INJ(a, b) { x0 = imad1(x0, one, (a)); x1 = imad1(x1, one, (b)); }
  TF_ROUND(13) TF_ROUND(15) TF_ROUND(26) TF_ROUND(6)
  TF_INJ(j1a, j1b)
  TF_ROUND(17) TF_ROUND(29) TF_ROUND(16) TF_ROUND(24)
  TF_INJ(j2a, j2b)
  TF_ROUND(13) TF_ROUND(15) TF_ROUND(26) TF_ROUND(6)
  TF_INJ(j3a, j3b)
  TF_ROUND(17) TF_ROUND(29) TF_ROUND(16) TF_ROUND(24)
  TF_INJ(j4a, j4b)
  TF_ROUND(13) TF_ROUND(15) TF_ROUND(26) TF_ROUND(6)
  TF_INJ(j5a, j5b)
#undef TF_ROUND
#undef TF_INJ
  return x0 ^ x1;
}

// Plain version (key derivation only; once per block).
__device__ __forceinline__ uint2 threefry2x32(uint32_t k0, uint32_t k1,
                                              uint32_t x0, uint32_t x1) {
  uint32_t k2 = k0 ^ k1 ^ 0x1BD11BDAu;
  x0 += k0; x1 += k1;
#define TF_ROUND(r) { x0 += x1; x1 = __funnelshift_l(x1, x1, (r)); x1 ^= x0; }
  TF_ROUND(13) TF_ROUND(15) TF_ROUND(26) TF_ROUND(6)
  x0 += k1; x1 += k2 + 1u;
  TF_ROUND(17) TF_ROUND(29) TF_ROUND(16) TF_ROUND(24)
  x0 += k2; x1 += k0 + 2u;
  TF_ROUND(13) TF_ROUND(15) TF_ROUND(26) TF_ROUND(6)
  x0 += k0; x1 += k1 + 3u;
  TF_ROUND(17) TF_ROUND(29) TF_ROUND(16) TF_ROUND(24)
  x0 += k1; x1 += k2 + 4u;
  TF_ROUND(13) TF_ROUND(15) TF_ROUND(26) TF_ROUND(6)
  x0 += k2; x1 += k0 + 5u;
#undef TF_ROUND
  return make_uint2(x0, x1);
}

#define JAX_LO (-0.99999994f)          // nextafter(-1, 0) in fp32
#define NEG_LN2 (-0.69314718f)
// w = -ln2*lg2(y); branch "w < 5"  <=>  lg2(y) > 5/-ln2
#define LG2_BRANCH (-7.21347520f)

// XLA ErfInv32 (Giles) WITHOUT the final sqrt2 (folded into sd prescale).
__device__ __forceinline__ float erfinv_raw(float x) {
  float y = fmaf(-x, x, 1.0f);          // 1 - x^2
  float wl = lg2_approx(y);             // lg2(y); w = -ln2 * wl
  float p;
  if (wl > LG2_BRANCH) {                // common path (w < 5), ~99.66%
    float w = fmaf(wl, NEG_LN2, -2.5f); // w - 2.5 fused
    p = 2.81022636e-08f;
    p = fmaf(p, w, 3.43273939e-07f);
    p = fmaf(p, w, -3.5233877e-06f);
    p = fmaf(p, w, -4.39150654e-06f);
    p = fmaf(p, w, 0.00021858087f);
    p = fmaf(p, w, -0.00125372503f);
    p = fmaf(p, w, -0.00417768164f);
    p = fmaf(p, w, 0.246640727f);
    p = fmaf(p, w, 1.50140941f);
  } else {
    float w = sqrtf(wl * NEG_LN2) - 3.0f;
    p = -0.000200214257f;
    p = fmaf(p, w, 0.000100950558f);
    p = fmaf(p, w, 0.00134934322f);
    p = fmaf(p, w, -0.00367342844f);
    p = fmaf(p, w, 0.00573950773f);
    p = fmaf(p, w, -0.0076224613f);
    p = fmaf(p, w, 0.00943887047f);
    p = fmaf(p, w, 1.00167406f);
    p = fmaf(p, w, 2.83297682f);
  }
  return p * x;
}

__device__ __forceinline__ float bits_to_eps_raw(uint32_t bits) {
  float g = __uint_as_float(mantissa_to_one_two(bits));  // [1, 2)
  float f = g - 1.0f;                                    // exact
  float u = fmaf(f, 2.0f, JAX_LO);   // == XLA mul+add; clamp is a proven no-op
  return erfinv_raw(u);              // sqrt2 folded into sd prescale
}

#define LOG2E 1.44269504f
#define SQRT2_LOG2E 2.04009342f       // sqrt(2) * log2(e)

__global__ __launch_bounds__(128, 9)
void hs_main_kernel(const float* __restrict__ in, float* __restrict__ out) {
  __shared__ uint2 sk[NSAMP];
  __shared__ float2 lgsd[NCH][128];   // (.x = logits*log2e, .y = std*sqrt2*log2e)
  int t = threadIdx.x;
  // Derive the 100 sample keys from jax.random.key(1) = (0, 1) in-block.
  if (t < NSAMP) sk[t] = threefry2x32(0u, 1u, 0u, (uint32_t)t);

  const uint32_t one = d_one;

  unsigned T = blockIdx.x * 128u + (unsigned)t;   // 0 .. 524287
  unsigned b = T >> 16;
  unsigned hw = T & 0xFFFFu;

  const float* pin = in + (size_t)b * (2 * NCH) * HW + hw;
#pragma unroll
  for (int c = 0; c < NCH; c++) {
    float l = pin[(size_t)c * HW];
    float s = __expf(pin[(size_t)(NCH + c) * HW]);
    lgsd[c][t] = make_float2(l * LOG2E, s * SQRT2_LOG2E);
  }
  __syncthreads();

  float acc[NCH];
#pragma unroll
  for (int c = 0; c < NCH; c++) acc[c] = 0.0f;

  const uint32_t ctrBase = b * (NCH * HW) + hw;   // flat idx of (b, 0, hw)

#pragma unroll 1
  for (int s = 0; s < NSAMP; s++) {
    const uint2 k = sk[s];
    const uint32_t k0 = k.x, k1 = k.y;
    const uint32_t k2 = k0 ^ k1 ^ 0x1BD11BDAu;
    const uint32_t j1b = k2 + 1u, j2b = k0 + 2u, j3b = k1 + 3u,
                   j4b = k2 + 4u, j5b = k0 + 5u;
    const uint32_t x1base = ctrBase + k1;   // counter lo + initial k1 inject
    float z[NCH];
#pragma unroll
    for (int c = 0; c < NCH; c++) {
      // counter = (0, ctrBase + c*HW); x0 init = 0 + k0.
      uint32_t x1 = imad1(x1base, one, (uint32_t)c << 16);
      uint32_t bits = threefry2x32_x(k0, x1,
                                     k1, j1b, k2, j2b, k0, j3b,
                                     k1, j4b, k2, j5b, one);
      float er = bits_to_eps_raw(bits);
      float2 ls = lgsd[c][t];
      z[c] = fmaf(er, ls.y, ls.x);       // log2-domain logits+eps*std
    }
    // softmax over channels in log2 domain — TREE max (depth 5, not 18-serial)
    float m;
    {
      float t0 = fmaxf(z[0], z[1]),  t1 = fmaxf(z[2], z[3]);
      float t2 = fmaxf(z[4], z[5]),  t3 = fmaxf(z[6], z[7]);
      float t4 = fmaxf(z[8], z[9]),  t5 = fmaxf(z[10], z[11]);
      float t6 = fmaxf(z[12], z[13]), t7 = fmaxf(z[14], z[15]);
      float t8 = fmaxf(z[16], z[17]);
      t0 = fmaxf(t0, t1); t2 = fmaxf(t2, t3); t4 = fmaxf(t4, t5);
      t6 = fmaxf(t6, t7); t8 = fmaxf(t8, z[18]);
      t0 = fmaxf(t0, t2); t4 = fmaxf(t4, t6);
      m = fmaxf(fmaxf(t0, t4), t8);
    }
#pragma unroll
    for (int c = 0; c < NCH; c++) z[c] = ex2_approx(z[c] - m);
    // TREE sum (depth 5)
    float sum;
    {
      float t0 = z[0] + z[1],  t1 = z[2] + z[3];
      float t2 = z[4] + z[5],  t3 = z[6] + z[7];
      float t4 = z[8] + z[9],  t5 = z[10] + z[11];
      float t6 = z[12] + z[13], t7 = z[14] + z[15];
      float t8 = z[16] + z[17];
      t0 += t1; t2 += t3; t4 += t5; t6 += t7; t8 += z[18];
      t0 += t2; t4 += t6;
      sum = (t0 + t4) + t8;
    }
    float inv = __fdividef(0.01f, sum);  // 1/NSAMP folded in
#pragma unroll
    for (int c = 0; c < NCH; c++) acc[c] = fmaf(z[c], inv, acc[c]);
  }

  float* pout = out + (size_t)b * NCH * HW + hw;
#pragma unroll
  for (int c = 0; c < NCH; c++) pout[(size_t)c * HW] = acc[c];
}

extern "C" void kernel_launch(void* const* d_in, const int* in_sizes, int n_in,
                              void* d_out, int out_size) {
  (void)in_sizes; (void)n_in; (void)out_size;
  const float* in = (const float*)d_in[0];
  float* out = (float*)d_out;

  // 8 batches * 65536 spatial = 524288 threads, one per (b, h, w)
  hs_main_kernel<<<4096, 128>>>(in, out);
}